// round 4
// baseline (speedup 1.0000x reference)
#include <cuda_runtime.h>
#include <math.h>
#include <float.h>

#define BB 2
#define NN 8192
#define CC 128
#define KK 8
#define MM (BB*NN)          // 16384 points total

#define WSTR 132            // padded smem stride for 128x128 weight tiles
#define QKV_ROWS 16
#define KNN_TILE 2048
#define ATT_WARPS 4

// ---- scratch (static device globals; no allocation allowed) ----
__device__ float g_q[MM*CC];
__device__ float g_k[MM*CC];
__device__ float g_v[MM*CC];
__device__ int   g_nbr[MM*KK];

// ================= Kernel 1: q,k,v = feats @ W^T =================
// One block: 16 rows x 128 cols, all three matrices (share the feats loads).
// W stored transposed in smem (wsm[c][cout], stride 132 -> conflict-free).
__global__ void __launch_bounds__(128)
qkv_kernel(const float* __restrict__ feats,
           const float* __restrict__ Wq,
           const float* __restrict__ Wk,
           const float* __restrict__ Wv)
{
    extern __shared__ float smem[];
    float* wq_sm = smem;                         // 128*WSTR
    float* wk_sm = wq_sm + CC*WSTR;
    float* wv_sm = wk_sm + CC*WSTR;
    float* f_sm  = wv_sm + CC*WSTR;              // QKV_ROWS*128

    const int tid  = threadIdx.x;
    const int row0 = blockIdx.x * QKV_ROWS;

    for (int e = tid; e < CC*CC; e += 128) {
        int cout = e >> 7, c = e & 127;
        wq_sm[c*WSTR + cout] = Wq[e];
        wk_sm[c*WSTR + cout] = Wk[e];
        wv_sm[c*WSTR + cout] = Wv[e];
    }
    for (int e = tid; e < QKV_ROWS*CC; e += 128)
        f_sm[e] = feats[row0*CC + e];
    __syncthreads();

    float aq[QKV_ROWS], ak[QKV_ROWS], av[QKV_ROWS];
#pragma unroll
    for (int i = 0; i < QKV_ROWS; ++i) { aq[i] = 0.f; ak[i] = 0.f; av[i] = 0.f; }

    const int t = tid;   // output column
#pragma unroll 4
    for (int c = 0; c < CC; ++c) {
        float wq = wq_sm[c*WSTR + t];
        float wk = wk_sm[c*WSTR + t];
        float wv = wv_sm[c*WSTR + t];
#pragma unroll
        for (int i = 0; i < QKV_ROWS; ++i) {
            float f = f_sm[i*CC + c];            // broadcast
            aq[i] = fmaf(f, wq, aq[i]);
            ak[i] = fmaf(f, wk, ak[i]);
            av[i] = fmaf(f, wv, av[i]);
        }
    }
#pragma unroll
    for (int i = 0; i < QKV_ROWS; ++i) {
        int o = (row0 + i)*CC + t;
        g_q[o] = aq[i]; g_k[o] = ak[i]; g_v[o] = av[i];
    }
}

// ================= Kernel 2: brute-force KNN (K=8) =================
// One thread = one query point; candidates tiled into smem as float4.
// Strict '<' insertion over ascending candidate index == top_k tie-breaking.
__global__ void __launch_bounds__(256)
knn_kernel(const float* __restrict__ coords)
{
    __shared__ float4 tile[KNN_TILE];            // 32 KB
    const int b = blockIdx.y;
    const int n = blockIdx.x * 256 + threadIdx.x;
    const float* cb = coords + (size_t)b * NN * 3;

    const float qx = cb[n*3+0], qy = cb[n*3+1], qz = cb[n*3+2];

    float best[KK]; int bi[KK];
#pragma unroll
    for (int s = 0; s < KK; ++s) { best[s] = FLT_MAX; bi[s] = 0; }

    for (int ts = 0; ts < NN; ts += KNN_TILE) {
        __syncthreads();
        for (int j = threadIdx.x; j < KNN_TILE; j += 256) {
            const float* p = cb + (size_t)(ts + j) * 3;
            tile[j] = make_float4(p[0], p[1], p[2], 0.f);
        }
        __syncthreads();
#pragma unroll 4
        for (int j = 0; j < KNN_TILE; ++j) {
            float4 p = tile[j];
            float dx = qx - p.x, dy = qy - p.y, dz = qz - p.z;
            float d2 = fmaf(dx, dx, fmaf(dy, dy, dz*dz));
            if (d2 < best[KK-1]) {               // rarely taken
                float v = d2; int vi = ts + j;
#pragma unroll
                for (int s = 0; s < KK; ++s) {
                    if (v < best[s]) {
                        float tb = best[s]; int ti = bi[s];
                        best[s] = v; bi[s] = vi; v = tb; vi = ti;
                    }
                }
            }
        }
    }
#pragma unroll
    for (int s = 0; s < KK; ++s)
        g_nbr[((size_t)b*NN + n)*KK + s] = bi[s];
}

// ============ Kernel 3: gather-attention + out = agg @ Wo^T ============
// One warp per point; lane owns channels {l, l+32, l+64, l+96}.
__global__ void __launch_bounds__(128)
attn_kernel(const float* __restrict__ coords,
            const float* __restrict__ Wo,
            const float* __restrict__ lg_ptr,
            float* __restrict__ out)
{
    extern __shared__ float smem[];
    float* wo_sm  = smem;                        // 128*WSTR
    float* agg_sm = wo_sm + CC*WSTR;             // ATT_WARPS*128

    const int tid = threadIdx.x;
    for (int e = tid; e < CC*CC; e += 128) {
        int cout = e >> 7, c = e & 127;
        wo_sm[c*WSTR + cout] = Wo[e];
    }
    __syncthreads();

    const float log_gamma = lg_ptr[0];
    const float inv_sqrtC = 0.08838834764831845f;   // 1/sqrt(128)

    const int warp = tid >> 5, lane = tid & 31;
    const int gwarp  = blockIdx.x * ATT_WARPS + warp;
    const int nwarps = gridDim.x * ATT_WARPS;
    float* ag = agg_sm + warp * CC;

    for (int p = gwarp; p < MM; p += nwarps) {
        const int b = p >> 13;                   // p / NN
        const int n = p & (NN - 1);
        const int base = p * CC;

        const float q0 = g_q[base + lane];
        const float q1 = g_q[base + lane + 32];
        const float q2 = g_q[base + lane + 64];
        const float q3 = g_q[base + lane + 96];

        const float* cb = coords + (size_t)b * NN * 3;
        const float qx = cb[n*3], qy = cb[n*3+1], qz = cb[n*3+2];

        int nb[KK];
#pragma unroll
        for (int j = 0; j < KK; ++j) nb[j] = g_nbr[p*KK + j];   // uniform/bcast

        float sc[KK];
        float smax = -FLT_MAX;
#pragma unroll
        for (int j = 0; j < KK; ++j) {
            const int nbj = nb[j];
            const float* kr = g_k + ((size_t)b*NN + nbj)*CC;
            float part = q0*kr[lane] + q1*kr[lane+32]
                       + q2*kr[lane+64] + q3*kr[lane+96];
#pragma unroll
            for (int o = 16; o > 0; o >>= 1)
                part += __shfl_xor_sync(0xffffffffu, part, o);
            float dx = qx - cb[nbj*3], dy = qy - cb[nbj*3+1], dz = qz - cb[nbj*3+2];
            float d2 = dx*dx + dy*dy + dz*dz;
            float dist = (d2 > 0.f) ? sqrtf(d2) : 0.f;          // _safe_norm
            float s = part * inv_sqrtC * expf(log_gamma * dist);
            sc[j] = s;
            smax = fmaxf(smax, s);
        }

        float w[KK], ssum = 0.f;
#pragma unroll
        for (int j = 0; j < KK; ++j) { w[j] = expf(sc[j] - smax); ssum += w[j]; }
        const float inv = 1.f / ssum;
#pragma unroll
        for (int j = 0; j < KK; ++j) w[j] *= inv;

        float a0 = 0.f, a1 = 0.f, a2 = 0.f, a3 = 0.f;
#pragma unroll
        for (int j = 0; j < KK; ++j) {
            const float* vr = g_v + ((size_t)b*NN + nb[j])*CC;
            a0 = fmaf(w[j], vr[lane],      a0);
            a1 = fmaf(w[j], vr[lane + 32], a1);
            a2 = fmaf(w[j], vr[lane + 64], a2);
            a3 = fmaf(w[j], vr[lane + 96], a3);
        }
        ag[lane] = a0; ag[lane+32] = a1; ag[lane+64] = a2; ag[lane+96] = a3;
        __syncwarp();

        float o0 = 0.f, o1 = 0.f, o2 = 0.f, o3 = 0.f;
#pragma unroll 4
        for (int c = 0; c < CC; ++c) {
            float a = ag[c];                      // broadcast
            o0 = fmaf(a, wo_sm[c*WSTR + lane],      o0);
            o1 = fmaf(a, wo_sm[c*WSTR + lane + 32], o1);
            o2 = fmaf(a, wo_sm[c*WSTR + lane + 64], o2);
            o3 = fmaf(a, wo_sm[c*WSTR + lane + 96], o3);
        }
        float* orow = out + base;
        orow[lane] = o0; orow[lane+32] = o1; orow[lane+64] = o2; orow[lane+96] = o3;
        __syncwarp();                             // agg_sm reuse next iter
    }
}

// =========================== launcher ===========================
extern "C" void kernel_launch(void* const* d_in, const int* in_sizes, int n_in,
                              void* d_out, int out_size)
{
    const float* feats  = (const float*)d_in[0];
    const float* coords = (const float*)d_in[1];
    const float* Wq     = (const float*)d_in[2];
    const float* Wk     = (const float*)d_in[3];
    const float* Wv     = (const float*)d_in[4];
    const float* Wo     = (const float*)d_in[5];
    const float* lg     = (const float*)d_in[6];
    float* out = (float*)d_out;

    const int smem1 = (3*CC*WSTR + QKV_ROWS*CC) * (int)sizeof(float);   // ~206 KB
    const int smem3 = (CC*WSTR + ATT_WARPS*CC) * (int)sizeof(float);    // ~68 KB
    cudaFuncSetAttribute(qkv_kernel,  cudaFuncAttributeMaxDynamicSharedMemorySize, smem1);
    cudaFuncSetAttribute(attn_kernel, cudaFuncAttributeMaxDynamicSharedMemorySize, smem3);

    qkv_kernel<<<MM / QKV_ROWS, 128, smem1>>>(feats, Wq, Wk, Wv);
    knn_kernel<<<dim3(NN / 256, BB), 256>>>(coords);
    attn_kernel<<<296, 128, smem3>>>(coords, Wo, lg, out);
}

// round 5
// speedup vs baseline: 1.4238x; 1.4238x over previous
#include <cuda_runtime.h>
#include <math.h>
#include <float.h>

#define BB 2
#define NN 8192
#define CC 128
#define KK 8
#define MM (BB*NN)          // 16384 points total
#define WSTR 132            // padded smem stride for 128x128 weight tiles

// ---- scratch (static device globals; no allocation allowed) ----
__device__ float g_q[MM*CC];
__device__ float g_k[MM*CC];
__device__ float g_v[MM*CC];
__device__ int   g_nbr[MM*KK];

// ================= Kernel 1: q,k,v = feats @ W^T =================
// 128 blocks x 256 threads; 128 rows/block in 4 row-tiles of 32.
// Weights transposed in smem [c][cout] (stride 132, conflict-free).
// Thread = (column t, row-half h); 16 rows x 3 mats = 48 accumulators.
#define QKV_RPB 128
#define QKV_TROWS 32

__global__ void __launch_bounds__(256)
qkv_kernel(const float* __restrict__ feats,
           const float* __restrict__ Wq,
           const float* __restrict__ Wk,
           const float* __restrict__ Wv)
{
    extern __shared__ float smem[];
    float* wq_sm = smem;                         // 128*WSTR
    float* wk_sm = wq_sm + CC*WSTR;
    float* wv_sm = wk_sm + CC*WSTR;
    float* f_sm  = wv_sm + CC*WSTR;              // 32*128

    const int tid = threadIdx.x;
    const int t = tid & 127;                     // output column
    const int h = tid >> 7;                      // row half (0/1)
    const int row0 = blockIdx.x * QKV_RPB;

    // load weights transposed (float4 global reads)
    for (int e4 = tid; e4 < CC*CC/4; e4 += 256) {
        int idx = e4 * 4;
        int cout = idx >> 7, c = idx & 127;
        float4 a = ((const float4*)Wq)[e4];
        wq_sm[(c+0)*WSTR+cout]=a.x; wq_sm[(c+1)*WSTR+cout]=a.y;
        wq_sm[(c+2)*WSTR+cout]=a.z; wq_sm[(c+3)*WSTR+cout]=a.w;
        float4 b = ((const float4*)Wk)[e4];
        wk_sm[(c+0)*WSTR+cout]=b.x; wk_sm[(c+1)*WSTR+cout]=b.y;
        wk_sm[(c+2)*WSTR+cout]=b.z; wk_sm[(c+3)*WSTR+cout]=b.w;
        float4 cv = ((const float4*)Wv)[e4];
        wv_sm[(c+0)*WSTR+cout]=cv.x; wv_sm[(c+1)*WSTR+cout]=cv.y;
        wv_sm[(c+2)*WSTR+cout]=cv.z; wv_sm[(c+3)*WSTR+cout]=cv.w;
    }

    for (int tile = 0; tile < QKV_RPB/QKV_TROWS; ++tile) {
        __syncthreads();   // also orders weight stores before first compute
        const float4* fsrc = (const float4*)(feats + (size_t)(row0 + tile*QKV_TROWS)*CC);
        for (int e = tid; e < QKV_TROWS*CC/4; e += 256)
            ((float4*)f_sm)[e] = fsrc[e];
        __syncthreads();

        float aq[16], ak[16], av[16];
#pragma unroll
        for (int i = 0; i < 16; ++i) { aq[i]=0.f; ak[i]=0.f; av[i]=0.f; }

        const float* frow = f_sm + h*16*CC;
#pragma unroll 2
        for (int c = 0; c < CC; ++c) {
            float wqv = wq_sm[c*WSTR + t];
            float wkv = wk_sm[c*WSTR + t];
            float wvv = wv_sm[c*WSTR + t];
#pragma unroll
            for (int i = 0; i < 16; ++i) {
                float f = frow[i*CC + c];        // warp broadcast
                aq[i] = fmaf(f, wqv, aq[i]);
                ak[i] = fmaf(f, wkv, ak[i]);
                av[i] = fmaf(f, wvv, av[i]);
            }
        }
        const int rbase = row0 + tile*QKV_TROWS + h*16;
#pragma unroll
        for (int i = 0; i < 16; ++i) {
            int o = (rbase + i)*CC + t;
            g_q[o] = aq[i]; g_k[o] = ak[i]; g_v[o] = av[i];
        }
    }
}

// ================= Kernel 2: brute-force KNN (K=8) =================
// 4 slices per query. 512 threads = 128 queries x 4 slices.
// Full batch candidates (coords + |c|^2) resident in 128 KB smem.
// Score = |c|^2 - 2 q.c  (same expanded form as the reference cdist).
#define KNN_THREADS 512
#define KNN_QPB (KNN_THREADS/4)    // 128 queries per block
#define SLICE (NN/4)               // 2048 candidates per slice

// sorted ascending insert with early exit (indices all compile-time)
__device__ __forceinline__ void ins8(float v, int vi, float best[KK], int bi[KK])
{
    best[7] = v; bi[7] = vi;
    if (v < best[6]) { best[7]=best[6]; bi[7]=bi[6]; best[6]=v; bi[6]=vi;
    if (v < best[5]) { best[6]=best[5]; bi[6]=bi[5]; best[5]=v; bi[5]=vi;
    if (v < best[4]) { best[5]=best[4]; bi[5]=bi[4]; best[4]=v; bi[4]=vi;
    if (v < best[3]) { best[4]=best[3]; bi[4]=bi[3]; best[3]=v; bi[3]=vi;
    if (v < best[2]) { best[3]=best[2]; bi[3]=bi[2]; best[2]=v; bi[2]=vi;
    if (v < best[1]) { best[2]=best[1]; bi[2]=bi[1]; best[1]=v; bi[1]=vi;
    if (v < best[0]) { best[1]=best[0]; bi[1]=bi[0]; best[0]=v; bi[0]=vi;
    }}}}}}}
}

__global__ void __launch_bounds__(KNN_THREADS)
knn_kernel(const float* __restrict__ coords)
{
    extern __shared__ float4 cand[];             // NN entries = 128 KB
    const int tid = threadIdx.x;
    const int b = blockIdx.y;
    const int g = tid >> 2;                      // query within block
    const int s = tid & 3;                       // slice
    const int n = blockIdx.x * KNN_QPB + g;
    const float* cb = coords + (size_t)b * NN * 3;

    for (int j = tid; j < NN; j += KNN_THREADS) {
        float x = cb[j*3], y = cb[j*3+1], z = cb[j*3+2];
        cand[j] = make_float4(x, y, z, fmaf(x, x, fmaf(y, y, z*z)));
    }
    __syncthreads();

    const float qx = cb[n*3], qy = cb[n*3+1], qz = cb[n*3+2];
    const float qx2 = -2.f*qx, qy2 = -2.f*qy, qz2 = -2.f*qz;

    float best[KK]; int bi[KK];
#pragma unroll
    for (int r = 0; r < KK; ++r) { best[r] = FLT_MAX; bi[r] = 0; }

    const int j0 = s * SLICE;
    // staggered start (offset s) keeps the 4 slice-addresses in distinct
    // bank groups for the broadcast LDS.128; wrap handles last s elements.
#pragma unroll 4
    for (int j = j0 + s; j < j0 + SLICE; ++j) {
        float4 p = cand[j];
        float sc = fmaf(qx2, p.x, fmaf(qy2, p.y, fmaf(qz2, p.z, p.w)));
        if (sc < best[7]) ins8(sc, j, best, bi);
    }
    for (int j = j0; j < j0 + s; ++j) {          // <=3 wrapped iterations
        float4 p = cand[j];
        float sc = fmaf(qx2, p.x, fmaf(qy2, p.y, fmaf(qz2, p.z, p.w)));
        if (sc < best[7]) ins8(sc, j, best, bi);
    }

    // merge the 4 sorted slice-lists: lanes s=1..3 -> slice leader (s==0).
    // Slices are ascending index ranges, so strict-< keeps top_k tie order.
    const unsigned lane = tid & 31;
    const unsigned lbase = lane & ~3u;
    for (int src = 1; src < 4; ++src) {
#pragma unroll
        for (int r = 0; r < KK; ++r) {
            float v  = __shfl_sync(0xffffffffu, best[r], lbase + src);
            int   vi = __shfl_sync(0xffffffffu, bi[r],   lbase + src);
            if (s == 0 && v < best[7]) ins8(v, vi, best, bi);
        }
    }
    if (s == 0) {
        int* o = g_nbr + ((size_t)b*NN + n)*KK;
#pragma unroll
        for (int r = 0; r < KK; ++r) o[r] = bi[r];
    }
}

// ============ Kernel 3: gather-attention + out = agg @ Wo^T ============
// One warp per point; lane owns channels {4l..4l+3} -> 128-bit gathers.
#define ATT_WARPS 8

__global__ void __launch_bounds__(256)
attn_kernel(const float* __restrict__ coords,
            const float* __restrict__ Wo,
            const float* __restrict__ lg_ptr,
            float* __restrict__ out)
{
    extern __shared__ float smem[];
    float* wo_sm  = smem;                        // 128*WSTR
    float* agg_sm = wo_sm + CC*WSTR;             // ATT_WARPS*128

    const int tid = threadIdx.x;
    for (int e4 = tid; e4 < CC*CC/4; e4 += 256) {
        int idx = e4 * 4;
        int cout = idx >> 7, c = idx & 127;
        float4 a = ((const float4*)Wo)[e4];
        wo_sm[(c+0)*WSTR+cout]=a.x; wo_sm[(c+1)*WSTR+cout]=a.y;
        wo_sm[(c+2)*WSTR+cout]=a.z; wo_sm[(c+3)*WSTR+cout]=a.w;
    }
    __syncthreads();

    const float log_gamma = lg_ptr[0];
    const float inv_sqrtC = 0.08838834764831845f;   // 1/sqrt(128)

    const int warp = tid >> 5, lane = tid & 31;
    const int gwarp  = blockIdx.x * ATT_WARPS + warp;
    const int nwarps = gridDim.x * ATT_WARPS;
    float* ag = agg_sm + warp * CC;

    for (int p = gwarp; p < MM; p += nwarps) {
        const int b = p >> 13;
        const int n = p & (NN - 1);
        const int base = p * CC;

        const float4 q4 = *(const float4*)(g_q + base + 4*lane);

        const float* cb = coords + (size_t)b * NN * 3;
        const float qx = cb[n*3], qy = cb[n*3+1], qz = cb[n*3+2];

        int nb[KK];
#pragma unroll
        for (int j = 0; j < KK; ++j) nb[j] = g_nbr[p*KK + j];

        float sc[KK];
        float smax = -FLT_MAX;
#pragma unroll
        for (int j = 0; j < KK; ++j) {
            const int m = nb[j];
            const float4 k4 = *((const float4*)(g_k + ((size_t)b*NN + m)*CC) + lane);
            float part = fmaf(q4.x, k4.x, fmaf(q4.y, k4.y,
                         fmaf(q4.z, k4.z, q4.w * k4.w)));
#pragma unroll
            for (int o = 16; o > 0; o >>= 1)
                part += __shfl_xor_sync(0xffffffffu, part, o);
            float dx = qx - cb[m*3], dy = qy - cb[m*3+1], dz = qz - cb[m*3+2];
            float d2 = fmaf(dx, dx, fmaf(dy, dy, dz*dz));
            float dist = (d2 > 0.f) ? sqrtf(d2) : 0.f;          // _safe_norm
            float sv = part * inv_sqrtC * __expf(log_gamma * dist);
            sc[j] = sv;
            smax = fmaxf(smax, sv);
        }

        float w[KK], ssum = 0.f;
#pragma unroll
        for (int j = 0; j < KK; ++j) { w[j] = __expf(sc[j] - smax); ssum += w[j]; }
        const float inv = 1.f / ssum;
#pragma unroll
        for (int j = 0; j < KK; ++j) w[j] *= inv;

        float4 a4 = make_float4(0.f, 0.f, 0.f, 0.f);
#pragma unroll
        for (int j = 0; j < KK; ++j) {
            const float4 v4 = *((const float4*)(g_v + ((size_t)b*NN + nb[j])*CC) + lane);
            a4.x = fmaf(w[j], v4.x, a4.x);
            a4.y = fmaf(w[j], v4.y, a4.y);
            a4.z = fmaf(w[j], v4.z, a4.z);
            a4.w = fmaf(w[j], v4.w, a4.w);
        }
        *((float4*)(ag + 4*lane)) = a4;
        __syncwarp();

        float4 o4 = make_float4(0.f, 0.f, 0.f, 0.f);
#pragma unroll 2
        for (int c = 0; c < CC; c += 4) {
            const float4 av = *(const float4*)(ag + c);          // broadcast
#pragma unroll
            for (int r = 0; r < 4; ++r) {
                float a = (r==0)?av.x:(r==1)?av.y:(r==2)?av.z:av.w;
                const float4 w4 = *(const float4*)(wo_sm + (c+r)*WSTR + 4*lane);
                o4.x = fmaf(a, w4.x, o4.x);
                o4.y = fmaf(a, w4.y, o4.y);
                o4.z = fmaf(a, w4.z, o4.z);
                o4.w = fmaf(a, w4.w, o4.w);
            }
        }
        *((float4*)(out + base + 4*lane)) = o4;
        __syncwarp();                             // agg_sm reuse next iter
    }
}

// =========================== launcher ===========================
extern "C" void kernel_launch(void* const* d_in, const int* in_sizes, int n_in,
                              void* d_out, int out_size)
{
    const float* feats  = (const float*)d_in[0];
    const float* coords = (const float*)d_in[1];
    const float* Wq     = (const float*)d_in[2];
    const float* Wk     = (const float*)d_in[3];
    const float* Wv     = (const float*)d_in[4];
    const float* Wo     = (const float*)d_in[5];
    const float* lg     = (const float*)d_in[6];
    float* out = (float*)d_out;

    const int smem1 = (3*CC*WSTR + QKV_TROWS*CC) * (int)sizeof(float);   // 219136
    const int smem2 = NN * (int)sizeof(float4);                          // 131072
    const int smem3 = (CC*WSTR + ATT_WARPS*CC) * (int)sizeof(float);     // 71680
    cudaFuncSetAttribute(qkv_kernel,  cudaFuncAttributeMaxDynamicSharedMemorySize, smem1);
    cudaFuncSetAttribute(knn_kernel,  cudaFuncAttributeMaxDynamicSharedMemorySize, smem2);
    cudaFuncSetAttribute(attn_kernel, cudaFuncAttributeMaxDynamicSharedMemorySize, smem3);

    qkv_kernel<<<MM / QKV_RPB, 256, smem1>>>(feats, Wq, Wk, Wv);
    knn_kernel<<<dim3(NN / KNN_QPB, BB), KNN_THREADS, smem2>>>(coords);
    attn_kernel<<<296, 256, smem3>>>(coords, Wo, lg, out);
}

// round 7
// speedup vs baseline: 2.0370x; 1.4307x over previous
#include <cuda_runtime.h>
#include <math.h>
#include <float.h>

#define BB 2
#define NN 8192
#define CC 128
#define KK 8
#define MM (BB*NN)          // 16384 points total
#define WSTR 132            // padded smem stride for 128x128 weight tiles

// ---- scratch (static device globals; no allocation allowed) ----
__device__ float g_q[MM*CC];
__device__ float g_k[MM*CC];
__device__ float g_v[MM*CC];
__device__ int   g_nbr[MM*KK];

// ================= Kernel 1: q|k|v = feats @ W^T (one matrix per block) ==
// grid (128, 3): y selects the matrix. 82 KB smem -> 2 blocks/SM.
// Weights transposed in smem [c][cout] (stride 132, conflict-free).
#define QKV_RPB 128
#define QKV_TROWS 32

__global__ void __launch_bounds__(256)
qkv_kernel(const float* __restrict__ feats,
           const float* __restrict__ Wq,
           const float* __restrict__ Wk,
           const float* __restrict__ Wv)
{
    const float* W = (blockIdx.y == 0) ? Wq : (blockIdx.y == 1) ? Wk : Wv;
    float* dst     = (blockIdx.y == 0) ? g_q : (blockIdx.y == 1) ? g_k : g_v;

    extern __shared__ float smem[];
    float* w_sm = smem;                          // 128*WSTR
    float* f_sm = w_sm + CC*WSTR;                // 32*128

    const int tid = threadIdx.x;
    const int t = tid & 127;                     // output column
    const int h = tid >> 7;                      // row half (0/1)
    const int row0 = blockIdx.x * QKV_RPB;

    // load weights transposed (float4 global reads, scalar smem stores)
    for (int e4 = tid; e4 < CC*CC/4; e4 += 256) {
        int idx = e4 * 4;
        int cout = idx >> 7, c = idx & 127;
        float4 a = ((const float4*)W)[e4];
        w_sm[(c+0)*WSTR+cout]=a.x; w_sm[(c+1)*WSTR+cout]=a.y;
        w_sm[(c+2)*WSTR+cout]=a.z; w_sm[(c+3)*WSTR+cout]=a.w;
    }

    for (int tile = 0; tile < QKV_RPB/QKV_TROWS; ++tile) {
        __syncthreads();   // orders weight stores before first compute too
        const float4* fsrc = (const float4*)(feats + (size_t)(row0 + tile*QKV_TROWS)*CC);
        for (int e = tid; e < QKV_TROWS*CC/4; e += 256)
            ((float4*)f_sm)[e] = fsrc[e];
        __syncthreads();

        float acc[16];
#pragma unroll
        for (int i = 0; i < 16; ++i) acc[i] = 0.f;

        const float* frow = f_sm + h*16*CC;
#pragma unroll 2
        for (int c4 = 0; c4 < CC/4; ++c4) {
            const int c = c4 * 4;
            float w0 = w_sm[(c+0)*WSTR + t];
            float w1 = w_sm[(c+1)*WSTR + t];
            float w2 = w_sm[(c+2)*WSTR + t];
            float w3 = w_sm[(c+3)*WSTR + t];
#pragma unroll
            for (int i = 0; i < 16; ++i) {
                float4 f4 = *(const float4*)(frow + i*CC + c);  // warp broadcast
                acc[i] = fmaf(f4.x, w0, acc[i]);
                acc[i] = fmaf(f4.y, w1, acc[i]);
                acc[i] = fmaf(f4.z, w2, acc[i]);
                acc[i] = fmaf(f4.w, w3, acc[i]);
            }
        }
        const int rbase = row0 + tile*QKV_TROWS + h*16;
#pragma unroll
        for (int i = 0; i < 16; ++i)
            dst[(rbase + i)*CC + t] = acc[i];
    }
}

// ================= Kernel 2: brute-force KNN (K=8) =================
// One WARP per query; lanes scan candidates in parallel against a single
// warp-shared threshold (best[7], replicated identically in all lanes).
// Insert events are warp-uniform -> no divergence; event count drops to
// ~8*ln(N) per query. Full batch candidates resident in 128 KB smem.
#define KNN_THREADS 1024
#define KNN_QPB (KNN_THREADS/32)   // 32 queries per block

// sorted ascending insert with early exit; warp-uniform callers only
__device__ __forceinline__ void ins8(float v, int vi, float best[KK], int bi[KK])
{
    best[7] = v; bi[7] = vi;
    if (v < best[6]) { best[7]=best[6]; bi[7]=bi[6]; best[6]=v; bi[6]=vi;
    if (v < best[5]) { best[6]=best[5]; bi[6]=bi[5]; best[5]=v; bi[5]=vi;
    if (v < best[4]) { best[5]=best[4]; bi[5]=bi[4]; best[4]=v; bi[4]=vi;
    if (v < best[3]) { best[4]=best[3]; bi[4]=bi[3]; best[3]=v; bi[3]=vi;
    if (v < best[2]) { best[3]=best[2]; bi[3]=bi[2]; best[2]=v; bi[2]=vi;
    if (v < best[1]) { best[2]=best[1]; bi[2]=bi[1]; best[1]=v; bi[1]=vi;
    if (v < best[0]) { best[1]=best[0]; bi[1]=bi[0]; best[0]=v; bi[0]=vi;
    }}}}}}}
}

__global__ void __launch_bounds__(KNN_THREADS)
knn_kernel(const float* __restrict__ coords)
{
    extern __shared__ float4 cand[];             // NN entries = 128 KB
    const int tid = threadIdx.x;
    const int b = blockIdx.y;
    const float* cb = coords + (size_t)b * NN * 3;

    for (int j = tid; j < NN; j += KNN_THREADS) {
        float x = cb[j*3], y = cb[j*3+1], z = cb[j*3+2];
        cand[j] = make_float4(x, y, z, fmaf(x, x, fmaf(y, y, z*z)));
    }
    __syncthreads();

    const int warp = tid >> 5, lane = tid & 31;
    const int n = blockIdx.x * KNN_QPB + warp;   // this warp's query

    const float4 qc = cand[n];
    const float qx2 = -2.f*qc.x, qy2 = -2.f*qc.y, qz2 = -2.f*qc.z;

    // top-8 replicated in every lane (kept identical by uniform updates)
    float best[KK]; int bi[KK];
#pragma unroll
    for (int r = 0; r < KK; ++r) { best[r] = FLT_MAX; bi[r] = 0; }

    // score = |c|^2 - 2 q.c  (reference's expanded cdist form, monotone)
    for (int base = 0; base < NN; base += 128) {
#pragma unroll
        for (int u = 0; u < 4; ++u) {
            const int j = base + u*32 + lane;    // coalesced LDS.128
            float4 p = cand[j];
            float sc = fmaf(qx2, p.x, fmaf(qy2, p.y, fmaf(qz2, p.z, p.w)));
            unsigned m = __ballot_sync(0xffffffffu, sc < best[7]);
            while (m) {                          // warp-uniform loop
                const int src = __ffs(m) - 1;
                m &= m - 1;
                float v = __shfl_sync(0xffffffffu, sc, src);
                if (v < best[7]) {               // recheck: threshold tightens
                    ins8(v, base + u*32 + src, best, bi);
                }
            }
        }
    }

    if (lane == 0) {
        int* o = g_nbr + ((size_t)b*NN + n)*KK;
#pragma unroll
        for (int r = 0; r < KK; ++r) o[r] = bi[r];
    }
}

// ============ Kernel 3: gather-attention + out = agg @ Wo^T ============
// One warp per point; lane owns channels {4l..4l+3} -> 128-bit gathers.
#define ATT_WARPS 8

__global__ void __launch_bounds__(256)
attn_kernel(const float* __restrict__ coords,
            const float* __restrict__ Wo,
            const float* __restrict__ lg_ptr,
            float* __restrict__ out)
{
    extern __shared__ float smem[];
    float* wo_sm  = smem;                        // 128*WSTR
    float* agg_sm = wo_sm + CC*WSTR;             // ATT_WARPS*128

    const int tid = threadIdx.x;
    for (int e4 = tid; e4 < CC*CC/4; e4 += 256) {
        int idx = e4 * 4;
        int cout = idx >> 7, c = idx & 127;
        float4 a = ((const float4*)Wo)[e4];
        wo_sm[(c+0)*WSTR+cout]=a.x; wo_sm[(c+1)*WSTR+cout]=a.y;
        wo_sm[(c+2)*WSTR+cout]=a.z; wo_sm[(c+3)*WSTR+cout]=a.w;
    }
    __syncthreads();

    const float log_gamma = lg_ptr[0];
    const float inv_sqrtC = 0.08838834764831845f;   // 1/sqrt(128)

    const int warp = tid >> 5, lane = tid & 31;
    const int gwarp  = blockIdx.x * ATT_WARPS + warp;
    const int nwarps = gridDim.x * ATT_WARPS;
    float* ag = agg_sm + warp * CC;

    for (int p = gwarp; p < MM; p += nwarps) {
        const int b = p >> 13;
        const int n = p & (NN - 1);
        const int base = p * CC;

        const float4 q4 = *(const float4*)(g_q + base + 4*lane);

        const float* cb = coords + (size_t)b * NN * 3;
        const float qx = cb[n*3], qy = cb[n*3+1], qz = cb[n*3+2];

        int nb[KK];
#pragma unroll
        for (int j = 0; j < KK; ++j) nb[j] = g_nbr[p*KK + j];

        float sc[KK];
        float smax = -FLT_MAX;
#pragma unroll
        for (int j = 0; j < KK; ++j) {
            const int m = nb[j];
            const float4 k4 = *((const float4*)(g_k + ((size_t)b*NN + m)*CC) + lane);
            float part = fmaf(q4.x, k4.x, fmaf(q4.y, k4.y,
                         fmaf(q4.z, k4.z, q4.w * k4.w)));
#pragma unroll
            for (int o = 16; o > 0; o >>= 1)
                part += __shfl_xor_sync(0xffffffffu, part, o);
            float dx = qx - cb[m*3], dy = qy - cb[m*3+1], dz = qz - cb[m*3+2];
            float d2 = fmaf(dx, dx, fmaf(dy, dy, dz*dz));
            float dist = (d2 > 0.f) ? sqrtf(d2) : 0.f;          // _safe_norm
            float sv = part * inv_sqrtC * __expf(log_gamma * dist);
            sc[j] = sv;
            smax = fmaxf(smax, sv);
        }

        float w[KK], ssum = 0.f;
#pragma unroll
        for (int j = 0; j < KK; ++j) { w[j] = __expf(sc[j] - smax); ssum += w[j]; }
        const float inv = 1.f / ssum;
#pragma unroll
        for (int j = 0; j < KK; ++j) w[j] *= inv;

        float4 a4 = make_float4(0.f, 0.f, 0.f, 0.f);
#pragma unroll
        for (int j = 0; j < KK; ++j) {
            const float4 v4 = *((const float4*)(g_v + ((size_t)b*NN + nb[j])*CC) + lane);
            a4.x = fmaf(w[j], v4.x, a4.x);
            a4.y = fmaf(w[j], v4.y, a4.y);
            a4.z = fmaf(w[j], v4.z, a4.z);
            a4.w = fmaf(w[j], v4.w, a4.w);
        }
        *((float4*)(ag + 4*lane)) = a4;
        __syncwarp();

        float4 o4 = make_float4(0.f, 0.f, 0.f, 0.f);
#pragma unroll 2
        for (int c = 0; c < CC; c += 4) {
            const float4 av = *(const float4*)(ag + c);          // broadcast
#pragma unroll
            for (int r = 0; r < 4; ++r) {
                float a = (r==0)?av.x:(r==1)?av.y:(r==2)?av.z:av.w;
                const float4 w4 = *(const float4*)(wo_sm + (c+r)*WSTR + 4*lane);
                o4.x = fmaf(a, w4.x, o4.x);
                o4.y = fmaf(a, w4.y, o4.y);
                o4.z = fmaf(a, w4.z, o4.z);
                o4.w = fmaf(a, w4.w, o4.w);
            }
        }
        *((float4*)(out + base + 4*lane)) = o4;
        __syncwarp();                             // agg_sm reuse next iter
    }
}

// =========================== launcher ===========================
extern "C" void kernel_launch(void* const* d_in, const int* in_sizes, int n_in,
                              void* d_out, int out_size)
{
    const float* feats  = (const float*)d_in[0];
    const float* coords = (const float*)d_in[1];
    const float* Wq     = (const float*)d_in[2];
    const float* Wk     = (const float*)d_in[3];
    const float* Wv     = (const float*)d_in[4];
    const float* Wo     = (const float*)d_in[5];
    const float* lg     = (const float*)d_in[6];
    float* out = (float*)d_out;

    const int smem1 = (CC*WSTR + QKV_TROWS*CC) * (int)sizeof(float);     // 83968
    const int smem2 = NN * (int)sizeof(float4);                          // 131072
    const int smem3 = (CC*WSTR + ATT_WARPS*CC) * (int)sizeof(float);     // 71680
    cudaFuncSetAttribute(qkv_kernel,  cudaFuncAttributeMaxDynamicSharedMemorySize, smem1);
    cudaFuncSetAttribute(knn_kernel,  cudaFuncAttributeMaxDynamicSharedMemorySize, smem2);
    cudaFuncSetAttribute(attn_kernel, cudaFuncAttributeMaxDynamicSharedMemorySize, smem3);

    qkv_kernel<<<dim3(MM / QKV_RPB, 3), 256, smem1>>>(feats, Wq, Wk, Wv);
    knn_kernel<<<dim3(NN / KNN_QPB, BB), KNN_THREADS, smem2>>>(coords);
    attn_kernel<<<296, 256, smem3>>>(coords, Wo, lg, out);
}

// round 8
// speedup vs baseline: 2.5321x; 1.2430x over previous
#include <cuda_runtime.h>
#include <math.h>
#include <float.h>

#define BB 2
#define NN 8192
#define CC 128
#define KK 8
#define MM (BB*NN)          // 16384 points total
#define WSTR 132            // padded smem stride for 128x128 weight tiles

// ---- scratch (static device globals; no allocation allowed) ----
__device__ float g_q[MM*CC];
__device__ float g_k[MM*CC];
__device__ float g_v[MM*CC];
__device__ int   g_nbr[MM*KK];

// ================= Kernel 1: q,k,v = feats @ W^T (fused) =================
// 148 blocks x 256 threads, grid-stride over 512 row-tiles of 32.
// Weights transposed in smem [c][cout] (stride 132). Thread = (lane=colgroup
// of 4 cols, warp=rowgroup of 4 rows): 3 mats x 4x4 = 48 fp32 accumulators.
// Inner c4 step: 16 LDS.128 per 192 FFMA.
#define QKV_TILES (MM/32)   // 512

__global__ void __launch_bounds__(256)
qkv_kernel(const float* __restrict__ feats,
           const float* __restrict__ Wq,
           const float* __restrict__ Wk,
           const float* __restrict__ Wv)
{
    extern __shared__ float smem[];
    float* wq_sm = smem;                         // 128*WSTR
    float* wk_sm = wq_sm + CC*WSTR;
    float* wv_sm = wk_sm + CC*WSTR;
    float* f_sm  = wv_sm + CC*WSTR;              // 32*128

    const int tid  = threadIdx.x;
    const int lane = tid & 31;                   // colgroup: cols 4*lane..+3
    const int warp = tid >> 5;                   // rowgroup: rows 4*warp..+3

    // load weights transposed (float4 global reads, scalar smem stores;
    // 16-way store conflicts here are amortized over ~3.5 tiles -> ~2%)
    for (int e4 = tid; e4 < CC*CC/4; e4 += 256) {
        int idx = e4 * 4;
        int cout = idx >> 7, c = idx & 127;
        float4 a = ((const float4*)Wq)[e4];
        wq_sm[(c+0)*WSTR+cout]=a.x; wq_sm[(c+1)*WSTR+cout]=a.y;
        wq_sm[(c+2)*WSTR+cout]=a.z; wq_sm[(c+3)*WSTR+cout]=a.w;
        float4 b = ((const float4*)Wk)[e4];
        wk_sm[(c+0)*WSTR+cout]=b.x; wk_sm[(c+1)*WSTR+cout]=b.y;
        wk_sm[(c+2)*WSTR+cout]=b.z; wk_sm[(c+3)*WSTR+cout]=b.w;
        float4 cv = ((const float4*)Wv)[e4];
        wv_sm[(c+0)*WSTR+cout]=cv.x; wv_sm[(c+1)*WSTR+cout]=cv.y;
        wv_sm[(c+2)*WSTR+cout]=cv.z; wv_sm[(c+3)*WSTR+cout]=cv.w;
    }

    for (int tile = blockIdx.x; tile < QKV_TILES; tile += gridDim.x) {
        __syncthreads();   // also orders weight stores before first compute
        const float4* fsrc = (const float4*)(feats + (size_t)tile*32*CC);
        for (int e = tid; e < 32*CC/4; e += 256)
            ((float4*)f_sm)[e] = fsrc[e];
        __syncthreads();

        float4 AQ[4], AK[4], AV[4];
#pragma unroll
        for (int i = 0; i < 4; ++i) {
            AQ[i] = make_float4(0.f,0.f,0.f,0.f);
            AK[i] = make_float4(0.f,0.f,0.f,0.f);
            AV[i] = make_float4(0.f,0.f,0.f,0.f);
        }

        const float* frow = f_sm + (warp*4)*CC;
        const int wcol = 4*lane;
#pragma unroll 2
        for (int c4 = 0; c4 < CC/4; ++c4) {
            const int c = 4*c4;
            float fs[4][4];
#pragma unroll
            for (int i = 0; i < 4; ++i) {
                float4 F = *(const float4*)(frow + i*CC + c);   // broadcast
                fs[i][0]=F.x; fs[i][1]=F.y; fs[i][2]=F.z; fs[i][3]=F.w;
            }
#pragma unroll
            for (int r = 0; r < 4; ++r) {
                const float4 wq4 = *(const float4*)(wq_sm + (c+r)*WSTR + wcol);
                const float4 wk4 = *(const float4*)(wk_sm + (c+r)*WSTR + wcol);
                const float4 wv4 = *(const float4*)(wv_sm + (c+r)*WSTR + wcol);
#pragma unroll
                for (int i = 0; i < 4; ++i) {
                    const float f = fs[i][r];
                    AQ[i].x = fmaf(f, wq4.x, AQ[i].x);
                    AQ[i].y = fmaf(f, wq4.y, AQ[i].y);
                    AQ[i].z = fmaf(f, wq4.z, AQ[i].z);
                    AQ[i].w = fmaf(f, wq4.w, AQ[i].w);
                    AK[i].x = fmaf(f, wk4.x, AK[i].x);
                    AK[i].y = fmaf(f, wk4.y, AK[i].y);
                    AK[i].z = fmaf(f, wk4.z, AK[i].z);
                    AK[i].w = fmaf(f, wk4.w, AK[i].w);
                    AV[i].x = fmaf(f, wv4.x, AV[i].x);
                    AV[i].y = fmaf(f, wv4.y, AV[i].y);
                    AV[i].z = fmaf(f, wv4.z, AV[i].z);
                    AV[i].w = fmaf(f, wv4.w, AV[i].w);
                }
            }
        }
        const int rbase = tile*32 + warp*4;
#pragma unroll
        for (int i = 0; i < 4; ++i) {
            const size_t o = (size_t)(rbase + i)*CC + wcol;
            *(float4*)(g_q + o) = AQ[i];
            *(float4*)(g_k + o) = AK[i];
            *(float4*)(g_v + o) = AV[i];
        }
    }
}

// ================= Kernel 2: brute-force KNN (K=8) =================
// One WARP per query; warp-shared threshold replicated in all lanes.
// Candidates tiled in TWO 64 KB halves -> 2 blocks/SM (wave 3.46 -> 1.73).
// min-of-4 single-ballot fast path skips insert machinery on clean batches.
#define KNN_THREADS 512
#define KNN_QPB (KNN_THREADS/32)   // 16 queries per block
#define HALF (NN/2)                // 4096 candidates per smem pass

// sorted ascending insert with early exit; warp-uniform callers only
__device__ __forceinline__ void ins8(float v, int vi, float best[KK], int bi[KK])
{
    best[7] = v; bi[7] = vi;
    if (v < best[6]) { best[7]=best[6]; bi[7]=bi[6]; best[6]=v; bi[6]=vi;
    if (v < best[5]) { best[6]=best[5]; bi[6]=bi[5]; best[5]=v; bi[5]=vi;
    if (v < best[4]) { best[5]=best[4]; bi[5]=bi[4]; best[4]=v; bi[4]=vi;
    if (v < best[3]) { best[4]=best[3]; bi[4]=bi[3]; best[3]=v; bi[3]=vi;
    if (v < best[2]) { best[3]=best[2]; bi[3]=bi[2]; best[2]=v; bi[2]=vi;
    if (v < best[1]) { best[2]=best[1]; bi[2]=bi[1]; best[1]=v; bi[1]=vi;
    if (v < best[0]) { best[1]=best[0]; bi[1]=bi[0]; best[0]=v; bi[0]=vi;
    }}}}}}}
}

__global__ void __launch_bounds__(KNN_THREADS)
knn_kernel(const float* __restrict__ coords)
{
    extern __shared__ float4 cand[];             // HALF entries = 64 KB
    const int tid = threadIdx.x;
    const int b = blockIdx.y;
    const float* cb = coords + (size_t)b * NN * 3;

    const int warp = tid >> 5, lane = tid & 31;
    const int n = blockIdx.x * KNN_QPB + warp;   // this warp's query

    const float qx = cb[n*3], qy = cb[n*3+1], qz = cb[n*3+2];
    const float qx2 = -2.f*qx, qy2 = -2.f*qy, qz2 = -2.f*qz;

    // top-8 replicated in every lane (kept identical by uniform updates)
    float best[KK]; int bi[KK];
#pragma unroll
    for (int r = 0; r < KK; ++r) { best[r] = FLT_MAX; bi[r] = 0; }

    // score = |c|^2 - 2 q.c  (reference's expanded cdist form, monotone)
    for (int pass = 0; pass < 2; ++pass) {
        __syncthreads();
        const float* src = cb + (size_t)pass*HALF*3;
        for (int j = tid; j < HALF; j += KNN_THREADS) {
            float x = src[j*3], y = src[j*3+1], z = src[j*3+2];
            cand[j] = make_float4(x, y, z, fmaf(x, x, fmaf(y, y, z*z)));
        }
        __syncthreads();

        const int gbase = pass * HALF;
        for (int base = 0; base < HALF; base += 128) {
            float sc[4];
#pragma unroll
            for (int u = 0; u < 4; ++u) {
                float4 p = cand[base + u*32 + lane];
                sc[u] = fmaf(qx2, p.x, fmaf(qy2, p.y, fmaf(qz2, p.z, p.w)));
            }
            float mn = fminf(fminf(sc[0], sc[1]), fminf(sc[2], sc[3]));
            if (__ballot_sync(0xffffffffu, mn < best[7])) {     // uniform
#pragma unroll
                for (int u = 0; u < 4; ++u) {
                    unsigned m = __ballot_sync(0xffffffffu, sc[u] < best[7]);
                    while (m) {                  // warp-uniform loop
                        const int src_l = __ffs(m) - 1;
                        m &= m - 1;
                        float v = __shfl_sync(0xffffffffu, sc[u], src_l);
                        if (v < best[7])         // recheck: threshold tightens
                            ins8(v, gbase + base + u*32 + src_l, best, bi);
                    }
                }
            }
        }
    }

    if (lane == 0) {
        int* o = g_nbr + ((size_t)b*NN + n)*KK;
#pragma unroll
        for (int r = 0; r < KK; ++r) o[r] = bi[r];
    }
}

// ============ Kernel 3: gather-attention + out = agg @ Wo^T ============
// One warp per point; lane owns channels {4l..4l+3} -> 128-bit gathers.
// k AND v rows prefetched before the score chain (one L2 round-trip).
#define ATT_WARPS 8

__global__ void __launch_bounds__(256, 2)
attn_kernel(const float* __restrict__ coords,
            const float* __restrict__ Wo,
            const float* __restrict__ lg_ptr,
            float* __restrict__ out)
{
    extern __shared__ float smem[];
    float* wo_sm  = smem;                        // 128*WSTR
    float* agg_sm = wo_sm + CC*WSTR;             // ATT_WARPS*128

    const int tid = threadIdx.x;
    for (int e4 = tid; e4 < CC*CC/4; e4 += 256) {
        int idx = e4 * 4;
        int cout = idx >> 7, c = idx & 127;
        float4 a = ((const float4*)Wo)[e4];
        wo_sm[(c+0)*WSTR+cout]=a.x; wo_sm[(c+1)*WSTR+cout]=a.y;
        wo_sm[(c+2)*WSTR+cout]=a.z; wo_sm[(c+3)*WSTR+cout]=a.w;
    }
    __syncthreads();

    const float log_gamma = lg_ptr[0];
    const float inv_sqrtC = 0.08838834764831845f;   // 1/sqrt(128)

    const int warp = tid >> 5, lane = tid & 31;
    const int gwarp  = blockIdx.x * ATT_WARPS + warp;
    const int nwarps = gridDim.x * ATT_WARPS;
    float* ag = agg_sm + warp * CC;

    for (int p = gwarp; p < MM; p += nwarps) {
        const int b = p >> 13;
        const int n = p & (NN - 1);
        const int base = p * CC;

        // neighbor indices: two LDG.128
        const int4 n0 = ((const int4*)(g_nbr + (size_t)p*KK))[0];
        const int4 n1 = ((const int4*)(g_nbr + (size_t)p*KK))[1];
        int nb[KK] = {n0.x, n0.y, n0.z, n0.w, n1.x, n1.y, n1.z, n1.w};

        const float4 q4 = *(const float4*)(g_q + base + 4*lane);

        // prefetch all 8 k-rows and 8 v-rows (independent -> full MLP)
        float4 k4[KK], v4[KK];
#pragma unroll
        for (int j = 0; j < KK; ++j) {
            const size_t ro = ((size_t)b*NN + nb[j])*CC;
            k4[j] = *((const float4*)(g_k + ro) + lane);
            v4[j] = *((const float4*)(g_v + ro) + lane);
        }

        const float* cb = coords + (size_t)b * NN * 3;
        const float qx = cb[n*3], qy = cb[n*3+1], qz = cb[n*3+2];

        float sc[KK];
        float smax = -FLT_MAX;
#pragma unroll
        for (int j = 0; j < KK; ++j) {
            const int m = nb[j];
            float part = fmaf(q4.x, k4[j].x, fmaf(q4.y, k4[j].y,
                         fmaf(q4.z, k4[j].z, q4.w * k4[j].w)));
#pragma unroll
            for (int o = 16; o > 0; o >>= 1)
                part += __shfl_xor_sync(0xffffffffu, part, o);
            float dx = qx - cb[m*3], dy = qy - cb[m*3+1], dz = qz - cb[m*3+2];
            float d2 = fmaf(dx, dx, fmaf(dy, dy, dz*dz));
            float dist = (d2 > 0.f) ? sqrtf(d2) : 0.f;          // _safe_norm
            float sv = part * inv_sqrtC * __expf(log_gamma * dist);
            sc[j] = sv;
            smax = fmaxf(smax, sv);
        }

        float w[KK], ssum = 0.f;
#pragma unroll
        for (int j = 0; j < KK; ++j) { w[j] = __expf(sc[j] - smax); ssum += w[j]; }
        const float inv = 1.f / ssum;
#pragma unroll
        for (int j = 0; j < KK; ++j) w[j] *= inv;

        float4 a4 = make_float4(0.f, 0.f, 0.f, 0.f);
#pragma unroll
        for (int j = 0; j < KK; ++j) {
            a4.x = fmaf(w[j], v4[j].x, a4.x);
            a4.y = fmaf(w[j], v4[j].y, a4.y);
            a4.z = fmaf(w[j], v4[j].z, a4.z);
            a4.w = fmaf(w[j], v4[j].w, a4.w);
        }
        *((float4*)(ag + 4*lane)) = a4;
        __syncwarp();

        float4 o4 = make_float4(0.f, 0.f, 0.f, 0.f);
#pragma unroll 2
        for (int c = 0; c < CC; c += 4) {
            const float4 av = *(const float4*)(ag + c);          // broadcast
#pragma unroll
            for (int r = 0; r < 4; ++r) {
                float a = (r==0)?av.x:(r==1)?av.y:(r==2)?av.z:av.w;
                const float4 w4 = *(const float4*)(wo_sm + (c+r)*WSTR + 4*lane);
                o4.x = fmaf(a, w4.x, o4.x);
                o4.y = fmaf(a, w4.y, o4.y);
                o4.z = fmaf(a, w4.z, o4.z);
                o4.w = fmaf(a, w4.w, o4.w);
            }
        }
        *((float4*)(out + base + 4*lane)) = o4;
        __syncwarp();                             // agg_sm reuse next iter
    }
}

// =========================== launcher ===========================
extern "C" void kernel_launch(void* const* d_in, const int* in_sizes, int n_in,
                              void* d_out, int out_size)
{
    const float* feats  = (const float*)d_in[0];
    const float* coords = (const float*)d_in[1];
    const float* Wq     = (const float*)d_in[2];
    const float* Wk     = (const float*)d_in[3];
    const float* Wv     = (const float*)d_in[4];
    const float* Wo     = (const float*)d_in[5];
    const float* lg     = (const float*)d_in[6];
    float* out = (float*)d_out;

    const int smem1 = (3*CC*WSTR + 32*CC) * (int)sizeof(float);          // 219136
    const int smem2 = HALF * (int)sizeof(float4);                        // 65536
    const int smem3 = (CC*WSTR + ATT_WARPS*CC) * (int)sizeof(float);     // 71680
    cudaFuncSetAttribute(qkv_kernel,  cudaFuncAttributeMaxDynamicSharedMemorySize, smem1);
    cudaFuncSetAttribute(knn_kernel,  cudaFuncAttributeMaxDynamicSharedMemorySize, smem2);
    cudaFuncSetAttribute(attn_kernel, cudaFuncAttributeMaxDynamicSharedMemorySize, smem3);

    qkv_kernel<<<148, 256, smem1>>>(feats, Wq, Wk, Wv);
    knn_kernel<<<dim3(NN / KNN_QPB, BB), KNN_THREADS, smem2>>>(coords);
    attn_kernel<<<296, 256, smem3>>>(coords, Wo, lg, out);
}